// round 15
// baseline (speedup 1.0000x reference)
#include <cuda_runtime.h>
#include <cstdint>

// ---------------------------------------------------------------------------
// SimpleSNN: B=4096, D_in=784, H=800, D_out=10, T=32
// Exactness invariant: every per-output accumulation chain keeps the exact
// sequential k/h order of the reference. s in {0,1}: fma(1,w,acc) == acc+w
// and fma(0,w,acc) == acc bitwise (sparse walk exact). Output columns are
// independent chains -> may be split across threads; the h-chain may NOT.
// Measured: predication (R6), row-pair-lane gemm1 (R8), 64-bit-chunk sparse
// walk (R14) pathological. gemm1 (R7 form) AT rt3-FFMA2 floor (~105us).
// This round: gemm2 = one thread per (row, output-pair), 5x parallelism.
// ---------------------------------------------------------------------------

#define B_     4096
#define DIN    784
#define H_     800
#define DOUT   10
#define TSTEPS 32
#define NW     25
#define NROWS  (TSTEPS * B_)       // 131072 (t,i) rows

__device__ unsigned g_xbits[B_ * NW];
__device__ float    g_cur1[B_ * H_];
__device__ unsigned g_spk[NW * NROWS];        // [w][row], row = t*B_ + i
__device__ float    g_cur2[NROWS * DOUT];

typedef unsigned long long ull;

// ------------------------------- helpers -----------------------------------
__device__ __forceinline__ ull pack2(float lo, float hi) {
    ull d;
    asm("mov.b64 %0, {%1, %2};" : "=l"(d) : "f"(lo), "f"(hi));
    return d;
}
__device__ __forceinline__ void unpack2(ull v, float &lo, float &hi) {
    asm("mov.b64 {%0, %1}, %2;" : "=f"(lo), "=f"(hi) : "l"(v));
}
__device__ __forceinline__ ull fma2(ull a, ull b, ull c) {
    ull d;
    asm("fma.rn.f32x2 %0, %1, %2, %3;" : "=l"(d) : "l"(a), "l"(b), "l"(c));
    return d;
}
__device__ __forceinline__ ull add2(ull a, ull b) {
    ull d;
    asm("add.rn.f32x2 %0, %1, %2;" : "=l"(d) : "l"(a), "l"(b));
    return d;
}

// ------------------------------- threefry ----------------------------------
#define ROTL32(x, d) (((x) << (d)) | ((x) >> (32 - (d))))

__device__ __forceinline__ unsigned threefry_xor(unsigned f) {
    const unsigned k0 = 0u, k1 = 42u;
    const unsigned k2 = 0x1BD11BDAu ^ k0 ^ k1;
    unsigned x0 = 0u + k0;
    unsigned x1 = f + k1;
#define TF_R(r) { x0 += x1; x1 = ROTL32(x1, r); x1 ^= x0; }
    TF_R(13) TF_R(15) TF_R(26) TF_R(6)   x0 += k1; x1 += k2 + 1u;
    TF_R(17) TF_R(29) TF_R(16) TF_R(24)  x0 += k2; x1 += k0 + 2u;
    TF_R(13) TF_R(15) TF_R(26) TF_R(6)   x0 += k0; x1 += k1 + 3u;
    TF_R(17) TF_R(29) TF_R(16) TF_R(24)  x0 += k1; x1 += k2 + 4u;
    TF_R(13) TF_R(15) TF_R(26) TF_R(6)   x0 += k2; x1 += k0 + 5u;
#undef TF_R
    return x0 ^ x1;
}

// K1: Bernoulli encode. One thread per (row, word).
__global__ void __launch_bounds__(256) k_encode(const float *__restrict__ x) {
    int idx = blockIdx.x * 256 + threadIdx.x;
    int i = idx / NW;
    int w = idx % NW;
    int nbits = (w == NW - 1) ? 16 : 32;
    long base = (long)i * DIN + w * 32;
    unsigned word = 0;
    for (int k = 0; k < nbits; k++) {
        long f = base + k;
        unsigned bits = threefry_xor((unsigned)f);
        float u = __uint_as_float((bits >> 9) | 0x3f800000u) - 1.0f;
        if (u < x[f]) word |= (1u << k);
    }
    g_xbits[idx] = word;
}

// K2: cur1 = xbits @ W1^T + b1.  BM=256 x BN=32, 256 threads, TM=4 TN=8.
// (R7/R10 form — at rt3 roofline, best-known.) Ascending j, FFMA2 dup mult.
__global__ void __launch_bounds__(256) k_gemm1(const float *__restrict__ W1,
                                               const float *__restrict__ b1) {
    __shared__ unsigned Aw[256];
    __shared__ __align__(16) float Bs[32][36];    // 36*4=144B rows, 16B aligned
    int tid = threadIdx.x;
    int rowbase = blockIdx.x * 256;
    int colbase = blockIdx.y * 32;
    int tc = tid & 3, tr = tid >> 2;              // 4 col-groups x 64 row-groups
    int c0 = tc * 8, r0 = tr * 4;

    ull acc[4][4];
#pragma unroll
    for (int r = 0; r < 4; r++)
#pragma unroll
        for (int q = 0; q < 4; q++) acc[r][q] = 0ull;

    for (int kw = 0; kw < NW; kw++) {
        Aw[tid] = g_xbits[(rowbase + tid) * NW + kw];
        {
            int c = tid >> 3;                     // 0..31
            int jv = (tid & 7) * 4;               // 0,4,..28
            int j = kw * 32 + jv;
            float4 bv = make_float4(0.f, 0.f, 0.f, 0.f);
            if (j < DIN)
                bv = *(const float4 *)(W1 + (long)(colbase + c) * DIN + j);
            Bs[jv + 0][c] = bv.x;
            Bs[jv + 1][c] = bv.y;
            Bs[jv + 2][c] = bv.z;
            Bs[jv + 3][c] = bv.w;
        }
        __syncthreads();

        unsigned a[4];
#pragma unroll
        for (int r = 0; r < 4; r++) a[r] = Aw[r0 + r];

#pragma unroll
        for (int jj = 0; jj < 32; jj++) {
            ulonglong2 p0 = *(const ulonglong2 *)&Bs[jj][c0];       // c0..c0+3
            ulonglong2 p1 = *(const ulonglong2 *)&Bs[jj][c0 + 4];   // c0+4..c0+7
#pragma unroll
            for (int r = 0; r < 4; r++) {
                float s = (a[r] & (1u << jj)) ? 1.0f : 0.0f;
                ull ss = pack2(s, s);
                acc[r][0] = fma2(ss, p0.x, acc[r][0]);
                acc[r][1] = fma2(ss, p0.y, acc[r][1]);
                acc[r][2] = fma2(ss, p1.x, acc[r][2]);
                acc[r][3] = fma2(ss, p1.y, acc[r][3]);
            }
        }
        __syncthreads();
    }

    float bb[8];
#pragma unroll
    for (int q = 0; q < 8; q++) bb[q] = b1[colbase + c0 + q];
#pragma unroll
    for (int r = 0; r < 4; r++) {
        int row = rowbase + r0 + r;
        float o0, o1, o2, o3, o4, o5, o6, o7;
        unpack2(acc[r][0], o0, o1);
        unpack2(acc[r][1], o2, o3);
        unpack2(acc[r][2], o4, o5);
        unpack2(acc[r][3], o6, o7);
        float4 lo = make_float4(o0 + bb[0], o1 + bb[1], o2 + bb[2], o3 + bb[3]);
        float4 hi = make_float4(o4 + bb[4], o5 + bb[5], o6 + bb[6], o7 + bb[7]);
        *(float4 *)(g_cur1 + (long)row * H_ + colbase + c0)     = lo;
        *(float4 *)(g_cur1 + (long)row * H_ + colbase + c0 + 4) = hi;
    }
}

// K3: layer-1 IF dynamics -> packed spike raster [w][t*B_+i]. One warp/(row,word).
__global__ void __launch_bounds__(256) k_spikegen() {
    int gtid = blockIdx.x * 256 + threadIdx.x;
    int wid  = gtid >> 5;
    int lane = gtid & 31;
    int i = wid / NW;
    int w = wid % NW;
    float c = g_cur1[(long)i * H_ + w * 32 + lane];
    float v = 0.0f;
    unsigned msave = 0;
#pragma unroll
    for (int t = 0; t < TSTEPS; t++) {
        float h1 = v + c;
        bool s = (h1 >= 1.0f);
        unsigned m = __ballot_sync(0xffffffffu, s);
        if (t == lane) msave = m;
        v = s ? 0.0f : h1;
    }
    g_spk[(long)w * NROWS + lane * B_ + i] = msave;
}

// K4: cur2 = spk1 @ W2^T + b2. One thread per (row, output-pair): 655360
// threads (20480 warps, full occupancy). Sparse ffs walk, ascending h
// (exact chain per output); 1 LDS.64 + 1 FADD2 per set bit. 5 consecutive
// lanes share a row: spike LDG broadcast, weight LDS 5-consecutive-ull.
__global__ void __launch_bounds__(256) k_gemm2(const float *__restrict__ W2,
                                               const float *__restrict__ b2) {
    __shared__ ull W2p[H_ * 5];                   // [h][op] pairs, 32000B
    for (int idx = threadIdx.x; idx < H_ * 5; idx += 256) {
        int h  = idx / 5;
        int op = idx % 5;
        W2p[idx] = pack2(W2[(2 * op) * H_ + h], W2[(2 * op + 1) * H_ + h]);
    }
    __syncthreads();

    int gid = blockIdx.x * 256 + threadIdx.x;     // 0 .. 655359
    int row = gid / 5;
    int op  = gid - row * 5;

    ull acc = 0;

    unsigned wd = g_spk[row];                     // prefetch w=0
    for (int w = 0; w < NW; w++) {
        unsigned cur = wd;
        int wn = (w + 1 < NW) ? (w + 1) : w;
        wd = g_spk[(long)wn * NROWS + row];       // prefetch next word

        const ull *bp = &W2p[w * 160 + op];
        while (cur) {
            int k = __ffs(cur) - 1;               // lowest set bit => h ascending
            cur &= cur - 1;
            acc = add2(acc, bp[k * 5]);
        }
    }

    float lo, hi;
    unpack2(acc, lo, hi);
    ((ull *)g_cur2)[(long)row * 5 + op] = pack2(lo + b2[2 * op], hi + b2[2 * op + 1]);
}

// K5: layer-2 IF scan -> spike counts. One thread per (i, o).
__global__ void __launch_bounds__(256) k_scan(float *__restrict__ out) {
    int id = blockIdx.x * 256 + threadIdx.x;
    int i = id / DOUT;
    int o = id % DOUT;
    float v = 0.0f, cnt = 0.0f;
#pragma unroll
    for (int t = 0; t < TSTEPS; t++) {
        float c2 = g_cur2[((long)t * B_ + i) * DOUT + o];
        float h2 = v + c2;
        bool s = (h2 >= 1.0f);
        cnt += s ? 1.0f : 0.0f;
        v = s ? 0.0f : h2;
    }
    out[id] = cnt;
}

// ---------------------------------------------------------------------------
extern "C" void kernel_launch(void *const *d_in, const int *in_sizes, int n_in,
                              void *d_out, int out_size) {
    const float *x  = (const float *)d_in[0];
    const float *W1 = (const float *)d_in[1];
    const float *b1 = (const float *)d_in[2];
    const float *W2 = (const float *)d_in[3];
    const float *b2 = (const float *)d_in[4];
    float *out = (float *)d_out;

    k_encode<<<400, 256>>>(x);

    k_gemm1<<<dim3(16, 25), 256>>>(W1, b1);

    k_spikegen<<<12800, 256>>>();

    k_gemm2<<<2560, 256>>>(W2, b2);

    k_scan<<<160, 256>>>(out);
}

// round 16
// speedup vs baseline: 1.1480x; 1.1480x over previous
#include <cuda_runtime.h>
#include <cstdint>

// ---------------------------------------------------------------------------
// SimpleSNN: B=4096, D_in=784, H=800, D_out=10, T=32
// Exactness invariant: every per-output accumulation chain keeps the exact
// sequential k/h order of the reference. s in {0,1}: fma(1,w,acc) == acc+w
// and fma(0,w,acc) == acc bitwise (sparse walk exact). Output columns are
// independent; the h-chain may never be split.
// Measured pathologies: predication (R6), row-pair-lane gemm1 (R8), 64-bit
// sparse chunks (R14), per-(row,opair) split (R15, 5x instruction bloat).
// Best-known: gemm1 R7 form (rt3-FFMA2 floor), gemm2 R11 sparse (59.4us).
// This round: fuse spikegen into gemm1 (tile cols == one spike word),
// deleting g_cur1 round-trip + one launch. gemm2 reverted to R11.
// ---------------------------------------------------------------------------

#define B_     4096
#define DIN    784
#define H_     800
#define DOUT   10
#define TSTEPS 32
#define NW     25
#define NROWS  (TSTEPS * B_)       // 131072 (t,i) rows

__device__ unsigned g_xbits[B_ * NW];
__device__ unsigned g_spk[NW * NROWS];        // [w][row], row = t*B_ + i
__device__ float    g_cur2[NROWS * DOUT];

typedef unsigned long long ull;

// ------------------------------- helpers -----------------------------------
__device__ __forceinline__ ull pack2(float lo, float hi) {
    ull d;
    asm("mov.b64 %0, {%1, %2};" : "=l"(d) : "f"(lo), "f"(hi));
    return d;
}
__device__ __forceinline__ void unpack2(ull v, float &lo, float &hi) {
    asm("mov.b64 {%0, %1}, %2;" : "=f"(lo), "=f"(hi) : "l"(v));
}
__device__ __forceinline__ ull fma2(ull a, ull b, ull c) {
    ull d;
    asm("fma.rn.f32x2 %0, %1, %2, %3;" : "=l"(d) : "l"(a), "l"(b), "l"(c));
    return d;
}
__device__ __forceinline__ ull add2(ull a, ull b) {
    ull d;
    asm("add.rn.f32x2 %0, %1, %2;" : "=l"(d) : "l"(a), "l"(b));
    return d;
}

// ------------------------------- threefry ----------------------------------
#define ROTL32(x, d) (((x) << (d)) | ((x) >> (32 - (d))))

__device__ __forceinline__ unsigned threefry_xor(unsigned f) {
    const unsigned k0 = 0u, k1 = 42u;
    const unsigned k2 = 0x1BD11BDAu ^ k0 ^ k1;
    unsigned x0 = 0u + k0;
    unsigned x1 = f + k1;
#define TF_R(r) { x0 += x1; x1 = ROTL32(x1, r); x1 ^= x0; }
    TF_R(13) TF_R(15) TF_R(26) TF_R(6)   x0 += k1; x1 += k2 + 1u;
    TF_R(17) TF_R(29) TF_R(16) TF_R(24)  x0 += k2; x1 += k0 + 2u;
    TF_R(13) TF_R(15) TF_R(26) TF_R(6)   x0 += k0; x1 += k1 + 3u;
    TF_R(17) TF_R(29) TF_R(16) TF_R(24)  x0 += k1; x1 += k2 + 4u;
    TF_R(13) TF_R(15) TF_R(26) TF_R(6)   x0 += k2; x1 += k0 + 5u;
#undef TF_R
    return x0 ^ x1;
}

// K1: Bernoulli encode. One thread per (row, word).
__global__ void __launch_bounds__(256) k_encode(const float *__restrict__ x) {
    int idx = blockIdx.x * 256 + threadIdx.x;
    int i = idx / NW;
    int w = idx % NW;
    int nbits = (w == NW - 1) ? 16 : 32;
    long base = (long)i * DIN + w * 32;
    unsigned word = 0;
    for (int k = 0; k < nbits; k++) {
        long f = base + k;
        unsigned bits = threefry_xor((unsigned)f);
        float u = __uint_as_float((bits >> 9) | 0x3f800000u) - 1.0f;
        if (u < x[f]) word |= (1u << k);
    }
    g_xbits[idx] = word;
}

// K2: FUSED cur1-GEMM + layer-1 IF spike generation.
// Phase 1 (R7-form GEMM): BM=256 x BN=32, 256 threads, TM=4 TN=8; per-output
// chain ascending j (exact); +bias; stage tile in smem Cs.
// Phase 2: tile cols ARE spike word blockIdx.y; 8 warps x 32 rows run the IF
// recurrence (lane = col, ballot per t) and write g_spk directly.
__global__ void __launch_bounds__(256) k_gemm1s(const float *__restrict__ W1,
                                                const float *__restrict__ b1) {
    __shared__ unsigned Aw[256];
    __shared__ __align__(16) float Bs[32][36];    // 144B rows, 16B aligned
    __shared__ __align__(16) float Cs[256][36];   // staged cur1 tile (36.9KB)
    int tid = threadIdx.x;
    int rowbase = blockIdx.x * 256;
    int colbase = blockIdx.y * 32;
    int tc = tid & 3, tr = tid >> 2;              // 4 col-groups x 64 row-groups
    int c0 = tc * 8, r0 = tr * 4;

    ull acc[4][4];
#pragma unroll
    for (int r = 0; r < 4; r++)
#pragma unroll
        for (int q = 0; q < 4; q++) acc[r][q] = 0ull;

    for (int kw = 0; kw < NW; kw++) {
        Aw[tid] = g_xbits[(rowbase + tid) * NW + kw];
        {
            int c = tid >> 3;                     // 0..31
            int jv = (tid & 7) * 4;               // 0,4,..28
            int j = kw * 32 + jv;
            float4 bv = make_float4(0.f, 0.f, 0.f, 0.f);
            if (j < DIN)
                bv = *(const float4 *)(W1 + (long)(colbase + c) * DIN + j);
            Bs[jv + 0][c] = bv.x;
            Bs[jv + 1][c] = bv.y;
            Bs[jv + 2][c] = bv.z;
            Bs[jv + 3][c] = bv.w;
        }
        __syncthreads();

        unsigned a[4];
#pragma unroll
        for (int r = 0; r < 4; r++) a[r] = Aw[r0 + r];

#pragma unroll
        for (int jj = 0; jj < 32; jj++) {
            ulonglong2 p0 = *(const ulonglong2 *)&Bs[jj][c0];       // c0..c0+3
            ulonglong2 p1 = *(const ulonglong2 *)&Bs[jj][c0 + 4];   // c0+4..c0+7
#pragma unroll
            for (int r = 0; r < 4; r++) {
                float s = (a[r] & (1u << jj)) ? 1.0f : 0.0f;
                ull ss = pack2(s, s);
                acc[r][0] = fma2(ss, p0.x, acc[r][0]);
                acc[r][1] = fma2(ss, p0.y, acc[r][1]);
                acc[r][2] = fma2(ss, p1.x, acc[r][2]);
                acc[r][3] = fma2(ss, p1.y, acc[r][3]);
            }
        }
        __syncthreads();
    }

    // Finalize with bias, stage into Cs
    float bb[8];
#pragma unroll
    for (int q = 0; q < 8; q++) bb[q] = b1[colbase + c0 + q];
#pragma unroll
    for (int r = 0; r < 4; r++) {
        int lrow = r0 + r;
        float o0, o1, o2, o3, o4, o5, o6, o7;
        unpack2(acc[r][0], o0, o1);
        unpack2(acc[r][1], o2, o3);
        unpack2(acc[r][2], o4, o5);
        unpack2(acc[r][3], o6, o7);
        *(float4 *)&Cs[lrow][c0] =
            make_float4(o0 + bb[0], o1 + bb[1], o2 + bb[2], o3 + bb[3]);
        *(float4 *)&Cs[lrow][c0 + 4] =
            make_float4(o4 + bb[4], o5 + bb[5], o6 + bb[6], o7 + bb[7]);
    }
    __syncthreads();

    // Phase 2: IF dynamics. Warp wp handles rows wp*32..wp*32+31; lane = col.
    int wp = tid >> 5;
    int lane = tid & 31;
    long spkbase = (long)blockIdx.y * NROWS;
    for (int rr = 0; rr < 32; rr++) {
        int lrow = wp * 32 + rr;
        float c = Cs[lrow][lane];
        float v = 0.0f;
        unsigned msave = 0;
#pragma unroll
        for (int t = 0; t < TSTEPS; t++) {
            float h1 = v + c;
            bool s = (h1 >= 1.0f);
            unsigned m = __ballot_sync(0xffffffffu, s);
            if (t == lane) msave = m;
            v = s ? 0.0f : h1;
        }
        g_spk[spkbase + lane * B_ + (rowbase + lrow)] = msave;
    }
}

// K4: cur2 = spk1 @ W2^T + b2. SPARSE (R11 form, best measured 59.4us):
// one row/thread walks set spike bits via ffs (ascending h => exact chain).
// f32x2 lanes = output pairs (2o, 2o+1).
__global__ void __launch_bounds__(256) k_gemm2(const float *__restrict__ W2,
                                               const float *__restrict__ b2) {
    __shared__ ull W2p[H_ * 5];                   // [h][5 output-pairs] = 32000B
    for (int idx = threadIdx.x; idx < H_ * 5; idx += 256) {
        int h  = idx / 5;
        int op = idx % 5;
        W2p[idx] = pack2(W2[(2 * op) * H_ + h], W2[(2 * op + 1) * H_ + h]);
    }
    __syncthreads();

    int row = blockIdx.x * 256 + threadIdx.x;     // 0 .. 131071

    ull a0 = 0, a1 = 0, a2 = 0, a3 = 0, a4 = 0;

    unsigned wd = g_spk[row];                     // prefetch w=0
    for (int w = 0; w < NW; w++) {
        unsigned cur = wd;
        int wn = (w + 1 < NW) ? (w + 1) : w;
        wd = g_spk[(long)wn * NROWS + row];       // prefetch next word

        const ull *bp = &W2p[w * 160];
        while (cur) {
            int k = __ffs(cur) - 1;               // lowest set bit => h ascending
            cur &= cur - 1;
            const ull *p = bp + k * 5;
            a0 = add2(a0, p[0]);
            a1 = add2(a1, p[1]);
            a2 = add2(a2, p[2]);
            a3 = add2(a3, p[3]);
            a4 = add2(a4, p[4]);
        }
    }

    float lo, hi;
    ull *outp = (ull *)(g_cur2 + (long)row * DOUT);
    unpack2(a0, lo, hi); outp[0] = pack2(lo + b2[0], hi + b2[1]);
    unpack2(a1, lo, hi); outp[1] = pack2(lo + b2[2], hi + b2[3]);
    unpack2(a2, lo, hi); outp[2] = pack2(lo + b2[4], hi + b2[5]);
    unpack2(a3, lo, hi); outp[3] = pack2(lo + b2[6], hi + b2[7]);
    unpack2(a4, lo, hi); outp[4] = pack2(lo + b2[8], hi + b2[9]);
}

// K5: layer-2 IF scan -> spike counts. One thread per (i, o).
__global__ void __launch_bounds__(256) k_scan(float *__restrict__ out) {
    int id = blockIdx.x * 256 + threadIdx.x;
    int i = id / DOUT;
    int o = id % DOUT;
    float v = 0.0f, cnt = 0.0f;
#pragma unroll
    for (int t = 0; t < TSTEPS; t++) {
        float c2 = g_cur2[((long)t * B_ + i) * DOUT + o];
        float h2 = v + c2;
        bool s = (h2 >= 1.0f);
        cnt += s ? 1.0f : 0.0f;
        v = s ? 0.0f : h2;
    }
    out[id] = cnt;
}

// ---------------------------------------------------------------------------
extern "C" void kernel_launch(void *const *d_in, const int *in_sizes, int n_in,
                              void *d_out, int out_size) {
    const float *x  = (const float *)d_in[0];
    const float *W1 = (const float *)d_in[1];
    const float *b1 = (const float *)d_in[2];
    const float *W2 = (const float *)d_in[3];
    const float *b2 = (const float *)d_in[4];
    float *out = (float *)d_out;

    k_encode<<<400, 256>>>(x);

    k_gemm1s<<<dim3(16, 25), 256>>>(W1, b1);

    k_gemm2<<<512, 256>>>(W2, b2);

    k_scan<<<160, 256>>>(out);
}